// round 4
// baseline (speedup 1.0000x reference)
#include <cuda_runtime.h>
#include <math.h>

// ---------------- scratch (device globals; no runtime allocation) -------------
__device__ float g_h[(size_t)50000 * 512];   // per-layer projected features
__device__ float g_as[50000 * 8];            // per-(node,head) source attention coef
__device__ float g_ad[50000 * 8];            // per-(node,head) dest attention coef
__device__ float g_f1[50000 * 64];           // layer outputs ping
__device__ float g_f2[50000 * 64];           // layer outputs pong
__device__ int   g_deg[50000];
__device__ int   g_rowptr[50001];
__device__ int   g_wp[50000];
__device__ int   g_col[450000];              // CSR (by dst) of src ids, incl self loops
__device__ int   g_is32;                     // edge_index dtype flag: 1 = int32, 0 = int64
__device__ int   g_bsum[128];
__device__ int   g_boff[128];

// buffer selectors: 0 = g_h, 1 = g_f1, 2 = g_f2
__device__ __forceinline__ float* selbuf(int s) {
    if (s == 0) return g_h;
    if (s == 1) return g_f1;
    return g_f2;
}

__device__ __forceinline__ int edge_at(const void* ei, long long idx, int is32) {
    return is32 ? ((const int*)ei)[idx] : (int)((const long long*)ei)[idx];
}

#define FMA2(c, a, b) asm("fma.rn.f32x2 %0, %1, %2, %0;" : "+l"(c) : "l"(a), "l"(b))

// ---------------- dtype detection: probe first 64 entries as int64 ------------
__global__ void k_detect(const void* __restrict__ ei, int n) {
    if (threadIdx.x != 0 || blockIdx.x != 0) return;
    const long long* p = (const long long*)ei;
    int bad = 0;
    for (int i = 0; i < 64; i++) {
        long long v = p[i];
        if (v < 0 || v >= (long long)n) bad = 1;
    }
    g_is32 = bad;
}

// ---------------- CSR build -------------
__global__ void k_initdeg(int n) {
    int i = blockIdx.x * blockDim.x + threadIdx.x;
    if (i < n) g_deg[i] = 1;  // self loop
}

__global__ void k_hist(const void* __restrict__ ei, int E, int n) {
    int i = blockIdx.x * blockDim.x + threadIdx.x;
    if (i >= E) return;
    int is32 = g_is32;
    int v = edge_at(ei, (long long)E + i, is32);
    if ((unsigned)v < (unsigned)n) atomicAdd(&g_deg[v], 1);
}

// hierarchical scan: A = per-block exclusive + block sums; B = scan block sums; C = add offsets
__global__ void k_scanA(int n) {
    __shared__ int sh[32];
    int t = threadIdx.x;
    int idx = blockIdx.x * 1024 + t;
    int v = (idx < n) ? g_deg[idx] : 0;
    int x = v;
    #pragma unroll
    for (int o = 1; o < 32; o <<= 1) {
        int y = __shfl_up_sync(0xffffffffu, x, o);
        if ((t & 31) >= o) x += y;
    }
    if ((t & 31) == 31) sh[t >> 5] = x;
    __syncthreads();
    if (t < 32) {
        int y = sh[t];
        #pragma unroll
        for (int o = 1; o < 32; o <<= 1) {
            int z = __shfl_up_sync(0xffffffffu, y, o);
            if (t >= o) y += z;
        }
        sh[t] = y;
    }
    __syncthreads();
    int off = ((t >> 5) > 0) ? sh[(t >> 5) - 1] : 0;
    int excl = x - v + off;
    if (idx < n) g_rowptr[idx] = excl;
    if (t == 1023) g_bsum[blockIdx.x] = excl + v;
}

__global__ void k_scanB(int nb, int n) {
    if (threadIdx.x != 0) return;
    int acc = 0;
    for (int i = 0; i < nb; i++) { int x = g_bsum[i]; g_boff[i] = acc; acc += x; }
    g_rowptr[n] = acc;
}

__global__ void k_scanC(int n) {
    int idx = blockIdx.x * blockDim.x + threadIdx.x;
    if (idx >= n) return;
    int v = g_rowptr[idx] + g_boff[idx >> 10];
    g_rowptr[idx] = v;
    g_wp[idx] = v;
}

__global__ void k_fill(const void* __restrict__ ei, int E, int n) {
    int i = blockIdx.x * blockDim.x + threadIdx.x;
    if (i >= E + n) return;
    int is32 = g_is32;
    int v, s;
    if (i < E) {
        s = edge_at(ei, i, is32);
        v = edge_at(ei, (long long)E + i, is32);
    } else {
        v = s = i - E;
    }
    if ((unsigned)v >= (unsigned)n || (unsigned)s >= (unsigned)n) return;
    int p = atomicAdd(&g_wp[v], 1);
    if ((unsigned)p < (unsigned)(E + n)) g_col[p] = s;
}

// ---------------- f32x2 SGEMM: C[M,N] = A[M,K] @ B[K,N] (+bias, relu) ----------
// BM=128, BK=8, 256 threads. M-pairs packed in acc; B duplicated into both halves.
template <int BN, bool BIAS, bool RELU>
__global__ void __launch_bounds__(256) k_gemm2(
        const float* __restrict__ Aext, const float* __restrict__ B,
        const float* __restrict__ bias, int asel, int csel,
        int M, int N, int K) {
    constexpr int BM = 128, BK = 8;
    constexpr int MN = BN / 16;  // micro-N per thread: 8 (BN=128) or 4 (BN=64)
    const float* __restrict__ A = (asel < 0) ? Aext : selbuf(asel);
    float* __restrict__ C = selbuf(csel);

    __shared__ float  As[2][BK][BM + 4];
    __shared__ float2 Bs[2][BK][BN];

    int tid = threadIdx.x;
    int ty = tid >> 4, tx = tid & 15;
    int bm = blockIdx.y * BM, bn = blockIdx.x * BN;

    int a_r = tid >> 1;            // 0..127
    int a_c = (tid & 1) << 2;      // 0 or 4
    int b_r, b_q;
    if (BN == 128) { b_r = tid >> 5; b_q = tid & 31; }
    else           { b_r = tid >> 4; b_q = tid & 15; }  // active when tid < 128

    unsigned long long acc[4][MN];
    #pragma unroll
    for (int i = 0; i < 4; i++)
        #pragma unroll
        for (int j = 0; j < MN; j++) acc[i][j] = 0ull;

    float4 ra, rb;
    int gm = bm + a_r;
    const bool bact = (BN == 128) || (tid < 128);
    int nt = K / BK;

    // ---- prologue: tile 0 ----
    {
        int k0 = 0;
        ra = make_float4(0.f, 0.f, 0.f, 0.f);
        if (gm < M) ra = *(const float4*)(A + (size_t)gm * K + k0 + a_c);
        rb = make_float4(0.f, 0.f, 0.f, 0.f);
        if (bact) {
            int gk = k0 + b_r, gn = bn + b_q * 4;
            if ((N & 3) == 0) {
                if (gn < N) rb = *(const float4*)(B + (size_t)gk * N + gn);
            } else {
                rb.x = (gn + 0 < N) ? B[(size_t)gk * N + gn + 0] : 0.f;
                rb.y = (gn + 1 < N) ? B[(size_t)gk * N + gn + 1] : 0.f;
                rb.z = (gn + 2 < N) ? B[(size_t)gk * N + gn + 2] : 0.f;
                rb.w = (gn + 3 < N) ? B[(size_t)gk * N + gn + 3] : 0.f;
            }
        }
        As[0][a_c + 0][a_r] = ra.x; As[0][a_c + 1][a_r] = ra.y;
        As[0][a_c + 2][a_r] = ra.z; As[0][a_c + 3][a_r] = ra.w;
        if (bact) {
            Bs[0][b_r][b_q * 4 + 0] = make_float2(rb.x, rb.x);
            Bs[0][b_r][b_q * 4 + 1] = make_float2(rb.y, rb.y);
            Bs[0][b_r][b_q * 4 + 2] = make_float2(rb.z, rb.z);
            Bs[0][b_r][b_q * 4 + 3] = make_float2(rb.w, rb.w);
        }
    }
    __syncthreads();

    for (int t = 0; t < nt; t++) {
        int cur = t & 1;
        bool more = (t + 1 < nt);
        if (more) {
            int k0 = (t + 1) * BK;
            ra = make_float4(0.f, 0.f, 0.f, 0.f);
            if (gm < M) ra = *(const float4*)(A + (size_t)gm * K + k0 + a_c);
            rb = make_float4(0.f, 0.f, 0.f, 0.f);
            if (bact) {
                int gk = k0 + b_r, gn = bn + b_q * 4;
                if ((N & 3) == 0) {
                    if (gn < N) rb = *(const float4*)(B + (size_t)gk * N + gn);
                } else {
                    rb.x = (gn + 0 < N) ? B[(size_t)gk * N + gn + 0] : 0.f;
                    rb.y = (gn + 1 < N) ? B[(size_t)gk * N + gn + 1] : 0.f;
                    rb.z = (gn + 2 < N) ? B[(size_t)gk * N + gn + 2] : 0.f;
                    rb.w = (gn + 3 < N) ? B[(size_t)gk * N + gn + 3] : 0.f;
                }
            }
        }
        #pragma unroll
        for (int kk = 0; kk < BK; kk++) {
            const unsigned long long* ap =
                reinterpret_cast<const unsigned long long*>(&As[cur][kk][ty * 8]);
            unsigned long long a0 = ap[0], a1 = ap[1], a2 = ap[2], a3 = ap[3];
            const unsigned long long* bp =
                reinterpret_cast<const unsigned long long*>(&Bs[cur][kk][tx * MN]);
            #pragma unroll
            for (int j = 0; j < MN; j++) {
                unsigned long long bj = bp[j];
                FMA2(acc[0][j], a0, bj);
                FMA2(acc[1][j], a1, bj);
                FMA2(acc[2][j], a2, bj);
                FMA2(acc[3][j], a3, bj);
            }
        }
        if (more) {
            int nb = cur ^ 1;
            As[nb][a_c + 0][a_r] = ra.x; As[nb][a_c + 1][a_r] = ra.y;
            As[nb][a_c + 2][a_r] = ra.z; As[nb][a_c + 3][a_r] = ra.w;
            if (bact) {
                Bs[nb][b_r][b_q * 4 + 0] = make_float2(rb.x, rb.x);
                Bs[nb][b_r][b_q * 4 + 1] = make_float2(rb.y, rb.y);
                Bs[nb][b_r][b_q * 4 + 2] = make_float2(rb.z, rb.z);
                Bs[nb][b_r][b_q * 4 + 3] = make_float2(rb.w, rb.w);
            }
        }
        __syncthreads();
    }

    // ---- epilogue ----
    #pragma unroll
    for (int mp = 0; mp < 4; mp++) {
        int r0 = bm + ty * 8 + mp * 2;
        #pragma unroll
        for (int j = 0; j < MN; j++) {
            int cn = bn + tx * MN + j;
            if (cn >= N) continue;
            unsigned long long v = acc[mp][j];
            float vlo = __uint_as_float((unsigned)(v & 0xffffffffull));
            float vhi = __uint_as_float((unsigned)(v >> 32));
            float bb = BIAS ? bias[cn] : 0.f;
            if (r0 < M) {
                float y = vlo + bb;
                if (RELU) y = fmaxf(y, 0.f);
                C[(size_t)r0 * N + cn] = y;
            }
            if (r0 + 1 < M) {
                float y = vhi + bb;
                if (RELU) y = fmaxf(y, 0.f);
                C[(size_t)(r0 + 1) * N + cn] = y;
            }
        }
    }
}

// ---------------- attention coefficients: warp per (node, head) ----------------
__global__ void k_attn(const float* __restrict__ att_s, const float* __restrict__ att_d,
                       int n, int H) {
    int gw = (blockIdx.x * blockDim.x + threadIdx.x) >> 5;
    int lane = threadIdx.x & 31;
    if (gw >= n * H) return;
    int head = gw % H;
    const float* hp = g_h + (size_t)gw * 64;   // gw = node*H + head; h row-major [n, H*64]
    float v0 = hp[lane], v1 = hp[lane + 32];
    float s0 = att_s[head * 64 + lane], s1 = att_s[head * 64 + 32 + lane];
    float d0 = att_d[head * 64 + lane], d1 = att_d[head * 64 + 32 + lane];
    float ss = v0 * s0 + v1 * s1;
    float dd = v0 * d0 + v1 * d1;
    #pragma unroll
    for (int o = 16; o > 0; o >>= 1) {
        ss += __shfl_xor_sync(0xffffffffu, ss, o);
        dd += __shfl_xor_sync(0xffffffffu, dd, o);
    }
    if (lane == 0) { g_as[gw] = ss; g_ad[gw] = dd; }
}

// ---------------- GAT gather: segment softmax + weighted mean over heads -------
template <int H, bool BNRELU>
__global__ void k_gather(const float* __restrict__ bias,
                         const float* __restrict__ bng, const float* __restrict__ bnb,
                         const float* __restrict__ bnm, const float* __restrict__ bnv,
                         int osel, int n) {
    float* __restrict__ out = selbuf(osel);
    int w = (blockIdx.x * blockDim.x + threadIdx.x) >> 5;
    int lane = threadIdx.x & 31;
    if (w >= n) return;
    int start = g_rowptr[w], end = g_rowptr[w + 1];

    float adl[H], m[H];
    #pragma unroll
    for (int h = 0; h < H; h++) { adl[h] = g_ad[w * H + h]; m[h] = -1e30f; }

    for (int j = start + lane; j < end; j += 32) {
        int s = g_col[j];
        #pragma unroll
        for (int h = 0; h < H; h++) {
            float e = g_as[s * H + h] + adl[h];
            e = (e > 0.f) ? e : 0.2f * e;
            m[h] = fmaxf(m[h], e);
        }
    }
    #pragma unroll
    for (int h = 0; h < H; h++)
        #pragma unroll
        for (int o = 16; o > 0; o >>= 1)
            m[h] = fmaxf(m[h], __shfl_xor_sync(0xffffffffu, m[h], o));

    float acc0[H], acc1[H], den[H];
    #pragma unroll
    for (int h = 0; h < H; h++) { acc0[h] = 0.f; acc1[h] = 0.f; den[h] = 0.f; }
    for (int j = start; j < end; j++) {
        int s = g_col[j];
        const float* hr = g_h + (size_t)s * (H * 64);
        #pragma unroll
        for (int h = 0; h < H; h++) {
            float e = g_as[s * H + h] + adl[h];
            e = (e > 0.f) ? e : 0.2f * e;
            float wgt = __expf(e - m[h]);
            den[h] += wgt;
            acc0[h] += wgt * hr[h * 64 + lane];
            acc1[h] += wgt * hr[h * 64 + 32 + lane];
        }
    }

    float y0 = 0.f, y1 = 0.f;
    #pragma unroll
    for (int h = 0; h < H; h++) {
        float inv = 1.f / (den[h] + 1e-16f);
        y0 += acc0[h] * inv;
        y1 += acc1[h] * inv;
    }
    const float invH = 1.f / (float)H;
    y0 *= invH; y1 *= invH;
    int c0 = lane, c1 = lane + 32;
    y0 += bias[c0]; y1 += bias[c1];
    if (BNRELU) {
        y0 = (y0 - bnm[c0]) * bng[c0] * rsqrtf(bnv[c0] + 1e-5f) + bnb[c0];
        y1 = (y1 - bnm[c1]) * bng[c1] * rsqrtf(bnv[c1] + 1e-5f) + bnb[c1];
        y0 = fmaxf(y0, 0.f);
        y1 = fmaxf(y1, 0.f);
    }
    out[(size_t)w * 64 + c0] = y0;
    out[(size_t)w * 64 + c1] = y1;
}

// ---------------- row softmax over C=50 classes (warp per node) ----------------
__global__ void k_softmax(float* __restrict__ out, int n, int C) {
    const float* __restrict__ logits = g_h;
    int w = (blockIdx.x * blockDim.x + threadIdx.x) >> 5;
    int lane = threadIdx.x & 31;
    if (w >= n) return;
    float v0 = (lane < C) ? logits[(size_t)w * C + lane] : -1e30f;
    float v1 = (lane + 32 < C) ? logits[(size_t)w * C + lane + 32] : -1e30f;
    float mx = fmaxf(v0, v1);
    #pragma unroll
    for (int o = 16; o > 0; o >>= 1) mx = fmaxf(mx, __shfl_xor_sync(0xffffffffu, mx, o));
    float e0 = (lane < C) ? __expf(v0 - mx) : 0.f;
    float e1 = (lane + 32 < C) ? __expf(v1 - mx) : 0.f;
    float s = e0 + e1;
    #pragma unroll
    for (int o = 16; o > 0; o >>= 1) s += __shfl_xor_sync(0xffffffffu, s, o);
    float inv = 1.f / s;
    if (lane < C) out[(size_t)w * C + lane] = e0 * inv;
    if (lane + 32 < C) out[(size_t)w * C + lane + 32] = e1 * inv;
}

// ---------------- host orchestration ----------------
extern "C" void kernel_launch(void* const* d_in, const int* in_sizes, int n_in,
                              void* d_out, int out_size) {
    const float* x   = (const float*)d_in[0];
    const void*  ei  = d_in[1];
    const float* W1  = (const float*)d_in[2];
    const float* as1 = (const float*)d_in[3];
    const float* ad1 = (const float*)d_in[4];
    const float* b1  = (const float*)d_in[5];
    const float* W2  = (const float*)d_in[6];
    const float* as2 = (const float*)d_in[7];
    const float* ad2 = (const float*)d_in[8];
    const float* b2  = (const float*)d_in[9];
    const float* W3  = (const float*)d_in[10];
    const float* as3 = (const float*)d_in[11];
    const float* ad3 = (const float*)d_in[12];
    const float* b3  = (const float*)d_in[13];
    const float* bn1g = (const float*)d_in[14];
    const float* bn1b = (const float*)d_in[15];
    const float* bn1m = (const float*)d_in[16];
    const float* bn1v = (const float*)d_in[17];
    const float* bn2g = (const float*)d_in[18];
    const float* bn2b = (const float*)d_in[19];
    const float* bn2m = (const float*)d_in[20];
    const float* bn2v = (const float*)d_in[21];
    const float* cW1 = (const float*)d_in[22];
    const float* cb1 = (const float*)d_in[23];
    const float* cW2 = (const float*)d_in[24];
    const float* cb2 = (const float*)d_in[25];

    int n = in_sizes[0] / 256;   // 50000
    int E = in_sizes[1] / 2;     // 400000
    float* out = (float*)d_out;
    int nblk = (n + 1023) / 1024;

    // edge dtype detection + CSR by dst (with self loops)
    k_detect<<<1, 32>>>(ei, n);
    k_initdeg<<<(n + 255) / 256, 256>>>(n);
    k_hist<<<(E + 255) / 256, 256>>>(ei, E, n);
    k_scanA<<<nblk, 1024>>>(n);
    k_scanB<<<1, 32>>>(nblk, n);
    k_scanC<<<(n + 255) / 256, 256>>>(n);
    k_fill<<<(E + n + 255) / 256, 256>>>(ei, E, n);

    // layer 1: H=8   (h = x @ W1 -> g_h[ n x 512 ])
    {
        dim3 grid(512 / 128, (n + 127) / 128);
        k_gemm2<128, false, false><<<grid, 256>>>(x, W1, nullptr, -1, 0, n, 512, 256);
    }
    k_attn<<<(n * 8 * 32 + 255) / 256, 256>>>(as1, ad1, n, 8);
    k_gather<8, true><<<(n * 32 + 255) / 256, 256>>>(b1, bn1g, bn1b, bn1m, bn1v, 1, n);

    // layer 2: H=4   (h = f1 @ W2 -> g_h[ n x 256 ])
    {
        dim3 grid(256 / 128, (n + 127) / 128);
        k_gemm2<128, false, false><<<grid, 256>>>(nullptr, W2, nullptr, 1, 0, n, 256, 64);
    }
    k_attn<<<(n * 4 * 32 + 255) / 256, 256>>>(as2, ad2, n, 4);
    k_gather<4, true><<<(n * 32 + 255) / 256, 256>>>(b2, bn2g, bn2b, bn2m, bn2v, 2, n);

    // layer 3: H=1, concat   (h = f2 @ W3 -> g_h[ n x 64 ])
    {
        dim3 grid(1, (n + 127) / 128);
        k_gemm2<64, false, false><<<grid, 256>>>(nullptr, W3, nullptr, 2, 0, n, 64, 64);
    }
    k_attn<<<(n * 1 * 32 + 255) / 256, 256>>>(as3, ad3, n, 1);
    k_gather<1, false><<<(n * 32 + 255) / 256, 256>>>(b3, nullptr, nullptr, nullptr, nullptr, 1, n);

    // classifier
    {
        dim3 grid(1, (n + 127) / 128);
        k_gemm2<64, true, true><<<grid, 256>>>(nullptr, cW1, cb1, 1, 2, n, 64, 64);
    }
    {
        dim3 grid(1, (n + 127) / 128);
        k_gemm2<64, true, false><<<grid, 256>>>(nullptr, cW2, cb2, 2, 0, n, 50, 64);
    }
    k_softmax<<<(n * 32 + 255) / 256, 256>>>(out, n, 50);
}

// round 5
// speedup vs baseline: 2.1683x; 2.1683x over previous
#include <cuda_runtime.h>
#include <cuda_bf16.h>
#include <math.h>

// ---------------- scratch (device globals; no runtime allocation) -------------
__device__ float g_h[(size_t)50000 * 512];   // per-layer projected features
__device__ float g_as[50000 * 8];
__device__ float g_ad[50000 * 8];
__device__ float g_f1[50000 * 64];
__device__ float g_f2[50000 * 64];
__device__ int   g_deg[50000];
__device__ int   g_rowptr[50001];
__device__ int   g_wp[50000];
__device__ int   g_col[450000];
__device__ int   g_is32;
__device__ int   g_bsum[128];
__device__ int   g_boff[128];
__device__ __nv_bfloat16 g_ahi[(size_t)50000 * 256];
__device__ __nv_bfloat16 g_alo[(size_t)50000 * 256];
__device__ __nv_bfloat16 g_bhi[256 * 512];
__device__ __nv_bfloat16 g_blo[256 * 512];

__device__ __forceinline__ float* selbuf(int s) {
    if (s == 0) return g_h;
    if (s == 1) return g_f1;
    return g_f2;
}

__device__ __forceinline__ int edge_at(const void* ei, long long idx, int is32) {
    return is32 ? ((const int*)ei)[idx] : (int)((const long long*)ei)[idx];
}

// ---------------- dtype detection ------------
__global__ void k_detect(const void* __restrict__ ei, int n) {
    if (threadIdx.x != 0 || blockIdx.x != 0) return;
    const long long* p = (const long long*)ei;
    int bad = 0;
    for (int i = 0; i < 64; i++) {
        long long v = p[i];
        if (v < 0 || v >= (long long)n) bad = 1;
    }
    g_is32 = bad;
}

// ---------------- CSR build -------------
__global__ void k_initdeg(int n) {
    int i = blockIdx.x * blockDim.x + threadIdx.x;
    if (i < n) g_deg[i] = 1;
}

__global__ void k_hist(const void* __restrict__ ei, int E, int n) {
    int i = blockIdx.x * blockDim.x + threadIdx.x;
    if (i >= E) return;
    int v = edge_at(ei, (long long)E + i, g_is32);
    if ((unsigned)v < (unsigned)n) atomicAdd(&g_deg[v], 1);
}

__global__ void k_scanA(int n) {
    __shared__ int sh[32];
    int t = threadIdx.x;
    int idx = blockIdx.x * 1024 + t;
    int v = (idx < n) ? g_deg[idx] : 0;
    int x = v;
    #pragma unroll
    for (int o = 1; o < 32; o <<= 1) {
        int y = __shfl_up_sync(0xffffffffu, x, o);
        if ((t & 31) >= o) x += y;
    }
    if ((t & 31) == 31) sh[t >> 5] = x;
    __syncthreads();
    if (t < 32) {
        int y = sh[t];
        #pragma unroll
        for (int o = 1; o < 32; o <<= 1) {
            int z = __shfl_up_sync(0xffffffffu, y, o);
            if (t >= o) y += z;
        }
        sh[t] = y;
    }
    __syncthreads();
    int off = ((t >> 5) > 0) ? sh[(t >> 5) - 1] : 0;
    int excl = x - v + off;
    if (idx < n) g_rowptr[idx] = excl;
    if (t == 1023) g_bsum[blockIdx.x] = excl + v;
}

__global__ void k_scanB(int nb, int n) {
    if (threadIdx.x != 0) return;
    int acc = 0;
    for (int i = 0; i < nb; i++) { int x = g_bsum[i]; g_boff[i] = acc; acc += x; }
    g_rowptr[n] = acc;
}

__global__ void k_scanC(int n) {
    int idx = blockIdx.x * blockDim.x + threadIdx.x;
    if (idx >= n) return;
    int v = g_rowptr[idx] + g_boff[idx >> 10];
    g_rowptr[idx] = v;
    g_wp[idx] = v;
}

__global__ void k_fill(const void* __restrict__ ei, int E, int n) {
    int i = blockIdx.x * blockDim.x + threadIdx.x;
    if (i >= E + n) return;
    int is32 = g_is32;
    int v, s;
    if (i < E) {
        s = edge_at(ei, i, is32);
        v = edge_at(ei, (long long)E + i, is32);
    } else {
        v = s = i - E;
    }
    if ((unsigned)v >= (unsigned)n || (unsigned)s >= (unsigned)n) return;
    int p = atomicAdd(&g_wp[v], 1);
    if ((unsigned)p < (unsigned)(E + n)) g_col[p] = s;
}

// ---------------- bf16 split conversion ----------------
__global__ void k_cvtA(const float* __restrict__ src, int srcsel, int count) {
    int i = blockIdx.x * blockDim.x + threadIdx.x;
    if (i >= count) return;
    const float* s = (srcsel < 0) ? src : selbuf(srcsel);
    float v = s[i];
    __nv_bfloat16 hi = __float2bfloat16(v);
    float r = v - __bfloat162float(hi);
    g_ahi[i] = hi;
    g_alo[i] = __float2bfloat16(r);
}

__global__ void k_cvtB(const float* __restrict__ src, int count) {
    int i = blockIdx.x * blockDim.x + threadIdx.x;
    if (i >= count) return;
    float v = src[i];
    __nv_bfloat16 hi = __float2bfloat16(v);
    float r = v - __bfloat162float(hi);
    g_bhi[i] = hi;
    g_blo[i] = __float2bfloat16(r);
}

// ---------------- bf16 tensor-core GEMM (split fp32) ----------------
// C[M,N](f32) = sum over 3 segments: Ahi@Bhi + Ahi@Blo + Alo@Bhi
// Tiles: BM=128, BN=128, BK=32; 256 threads = 8 warps (2 x 4).
__device__ __forceinline__ void mma_bf16(float* d, const unsigned* a, const unsigned* b) {
    asm volatile(
        "mma.sync.aligned.m16n8k16.row.col.f32.bf16.bf16.f32 "
        "{%0,%1,%2,%3},{%4,%5,%6,%7},{%8,%9},{%0,%1,%2,%3};\n"
        : "+f"(d[0]), "+f"(d[1]), "+f"(d[2]), "+f"(d[3])
        : "r"(a[0]), "r"(a[1]), "r"(a[2]), "r"(a[3]), "r"(b[0]), "r"(b[1]));
}
__device__ __forceinline__ void ldsm_x4(unsigned* r, unsigned addr) {
    asm volatile("ldmatrix.sync.aligned.m8n8.x4.shared.b16 {%0,%1,%2,%3},[%4];"
        : "=r"(r[0]), "=r"(r[1]), "=r"(r[2]), "=r"(r[3]) : "r"(addr));
}
__device__ __forceinline__ void ldsm_x2t(unsigned* r, unsigned addr) {
    asm volatile("ldmatrix.sync.aligned.m8n8.x2.trans.shared.b16 {%0,%1},[%2];"
        : "=r"(r[0]), "=r"(r[1]) : "r"(addr));
}

// smem strides (bytes): A rows padded 32+8 bf16 = 80B; B rows padded 128+8 = 272B
#define ASTRIDE 80
#define BSTRIDE 272

__global__ void __launch_bounds__(256) k_bmma(int csel, int M, int N, int K) {
    float* __restrict__ C = selbuf(csel);
    __shared__ __align__(16) unsigned char smA[2][128 * ASTRIDE];
    __shared__ __align__(16) unsigned char smB[2][32 * BSTRIDE];

    const int tid = threadIdx.x, lane = tid & 31, wid = tid >> 5;
    const int wm = wid & 1, wn = wid >> 1;
    const int bm = blockIdx.y * 128, bn = blockIdx.x * 128;
    const int ktiles = K / 32, total = 3 * ktiles;

    const __nv_bfloat16* segA[3] = {g_ahi, g_ahi, g_alo};
    const __nv_bfloat16* segB[3] = {g_bhi, g_blo, g_bhi};

    float acc[4][4][4];
    #pragma unroll
    for (int i = 0; i < 4; i++)
        #pragma unroll
        for (int j = 0; j < 4; j++)
            #pragma unroll
            for (int q = 0; q < 4; q++) acc[i][j][q] = 0.f;

    auto loadTiles = [&](int buf, int it) {
        int seg = it / ktiles, kk = it % ktiles;
        const __nv_bfloat16* Ap = segA[seg];
        const __nv_bfloat16* Bp = segB[seg];
        int k0 = kk * 32;
        #pragma unroll
        for (int i = 0; i < 2; i++) {
            int c = tid * 2 + i;          // A: 512 chunks of 16B
            int r = c >> 2, cc = c & 3;
            int gm = bm + r;
            uint4 v = make_uint4(0, 0, 0, 0);
            if (gm < M) v = *(const uint4*)(Ap + (size_t)gm * K + k0 + cc * 8);
            *(uint4*)(smA[buf] + r * ASTRIDE + cc * 16) = v;
        }
        #pragma unroll
        for (int i = 0; i < 2; i++) {
            int c = tid * 2 + i;          // B: 512 chunks of 16B
            int r = c >> 4, cc = c & 15;
            int gn = bn + cc * 8;
            uint4 v = make_uint4(0, 0, 0, 0);
            if (gn < N) v = *(const uint4*)(Bp + (size_t)(k0 + r) * N + gn);
            *(uint4*)(smB[buf] + r * BSTRIDE + cc * 16) = v;
        }
    };

    loadTiles(0, 0);
    __syncthreads();

    for (int it = 0; it < total; it++) {
        int buf = it & 1;
        if (it + 1 < total) loadTiles(buf ^ 1, it + 1);

        unsigned aBase = (unsigned)__cvta_generic_to_shared(smA[buf]);
        unsigned bBase = (unsigned)__cvta_generic_to_shared(smB[buf]);
        int arow = (lane & 7) + ((lane >> 3) & 1) * 8;
        int ahalf = (lane >> 4) * 8;
        int bk = lane & 15;
        #pragma unroll
        for (int kt2 = 0; kt2 < 2; kt2++) {
            unsigned a[4][4], b[4][2];
            #pragma unroll
            for (int mt = 0; mt < 4; mt++) {
                unsigned addr = aBase + (wm * 64 + mt * 16 + arow) * ASTRIDE
                              + (kt2 * 16 + ahalf) * 2;
                ldsm_x4(a[mt], addr);
            }
            #pragma unroll
            for (int nt = 0; nt < 4; nt++) {
                unsigned addr = bBase + (kt2 * 16 + bk) * BSTRIDE
                              + (wn * 32 + nt * 8) * 2;
                ldsm_x2t(b[nt], addr);
            }
            #pragma unroll
            for (int mt = 0; mt < 4; mt++)
                #pragma unroll
                for (int nt = 0; nt < 4; nt++)
                    mma_bf16(acc[mt][nt], a[mt], b[nt]);
        }
        __syncthreads();
    }

    // epilogue: f32 direct to global
    #pragma unroll
    for (int mt = 0; mt < 4; mt++) {
        int r0 = bm + wm * 64 + mt * 16 + (lane >> 2);
        #pragma unroll
        for (int nt = 0; nt < 4; nt++) {
            int cn = bn + wn * 32 + nt * 8 + (lane & 3) * 2;
            if (cn + 1 < N || cn + 1 == N) {
                if (cn + 2 <= N) {
                    if (r0 < M) {
                        float2 v = make_float2(acc[mt][nt][0], acc[mt][nt][1]);
                        *(float2*)(C + (size_t)r0 * N + cn) = v;
                    }
                    if (r0 + 8 < M) {
                        float2 v = make_float2(acc[mt][nt][2], acc[mt][nt][3]);
                        *(float2*)(C + (size_t)(r0 + 8) * N + cn) = v;
                    }
                }
            }
        }
    }
}

// ---------------- fp32 SGEMM (R3, proven) for small GEMMs ----------------
template <bool BIAS, bool RELU>
__global__ void k_sgemm(const float* __restrict__ Aext, const float* __restrict__ B,
                        const float* __restrict__ bias, int asel, int csel,
                        int M, int N, int K) {
    const float* __restrict__ A = (asel < 0) ? Aext : selbuf(asel);
    float* __restrict__ C = selbuf(csel);
    __shared__ float As[16][68];
    __shared__ float Bs[16][68];
    int tid = threadIdx.x;
    int ty = tid >> 4, tx = tid & 15;
    int bm = blockIdx.y * 64, bn = blockIdx.x * 64;
    int ar = tid >> 2, ac = (tid & 3) << 2;
    int br = tid >> 4, bc = (tid & 15) << 2;
    float acc[4][4];
    #pragma unroll
    for (int i = 0; i < 4; i++)
        #pragma unroll
        for (int j = 0; j < 4; j++) acc[i][j] = 0.f;

    for (int k0 = 0; k0 < K; k0 += 16) {
        int gm = bm + ar;
        float4 av = make_float4(0.f, 0.f, 0.f, 0.f);
        if (gm < M) av = *(const float4*)(A + (size_t)gm * K + k0 + ac);
        As[ac + 0][ar] = av.x; As[ac + 1][ar] = av.y;
        As[ac + 2][ar] = av.z; As[ac + 3][ar] = av.w;

        int gk = k0 + br, gn = bn + bc;
        float4 bv;
        if (((N & 3) == 0) && (gn + 3 < N)) {
            bv = *(const float4*)(B + (size_t)gk * N + gn);
        } else {
            bv.x = (gn + 0 < N) ? B[(size_t)gk * N + gn + 0] : 0.f;
            bv.y = (gn + 1 < N) ? B[(size_t)gk * N + gn + 1] : 0.f;
            bv.z = (gn + 2 < N) ? B[(size_t)gk * N + gn + 2] : 0.f;
            bv.w = (gn + 3 < N) ? B[(size_t)gk * N + gn + 3] : 0.f;
        }
        Bs[br][bc + 0] = bv.x; Bs[br][bc + 1] = bv.y;
        Bs[br][bc + 2] = bv.z; Bs[br][bc + 3] = bv.w;
        __syncthreads();

        #pragma unroll
        for (int kk = 0; kk < 16; kk++) {
            float a[4], b[4];
            #pragma unroll
            for (int i = 0; i < 4; i++) a[i] = As[kk][ty * 4 + i];
            #pragma unroll
            for (int j = 0; j < 4; j++) b[j] = Bs[kk][tx * 4 + j];
            #pragma unroll
            for (int i = 0; i < 4; i++)
                #pragma unroll
                for (int j = 0; j < 4; j++) acc[i][j] += a[i] * b[j];
        }
        __syncthreads();
    }

    #pragma unroll
    for (int i = 0; i < 4; i++) {
        int row = bm + ty * 4 + i;
        if (row >= M) continue;
        #pragma unroll
        for (int j = 0; j < 4; j++) {
            int cn = bn + tx * 4 + j;
            if (cn >= N) continue;
            float v = acc[i][j];
            if (BIAS) v += bias[cn];
            if (RELU) v = fmaxf(v, 0.f);
            C[(size_t)row * N + cn] = v;
        }
    }
}

// ---------------- attention coefficients: warp per (node, head) ----------------
__global__ void k_attn(const float* __restrict__ att_s, const float* __restrict__ att_d,
                       int n, int H) {
    int gw = (blockIdx.x * blockDim.x + threadIdx.x) >> 5;
    int lane = threadIdx.x & 31;
    if (gw >= n * H) return;
    int head = gw % H;
    const float* hp = g_h + (size_t)gw * 64;
    float v0 = hp[lane], v1 = hp[lane + 32];
    float s0 = att_s[head * 64 + lane], s1 = att_s[head * 64 + 32 + lane];
    float d0 = att_d[head * 64 + lane], d1 = att_d[head * 64 + 32 + lane];
    float ss = v0 * s0 + v1 * s1;
    float dd = v0 * d0 + v1 * d1;
    #pragma unroll
    for (int o = 16; o > 0; o >>= 1) {
        ss += __shfl_xor_sync(0xffffffffu, ss, o);
        dd += __shfl_xor_sync(0xffffffffu, dd, o);
    }
    if (lane == 0) { g_as[gw] = ss; g_ad[gw] = dd; }
}

// ---------------- GAT gather ----------------
template <int H, bool BNRELU>
__global__ void k_gather(const float* __restrict__ bias,
                         const float* __restrict__ bng, const float* __restrict__ bnb,
                         const float* __restrict__ bnm, const float* __restrict__ bnv,
                         int osel, int n) {
    float* __restrict__ out = selbuf(osel);
    int w = (blockIdx.x * blockDim.x + threadIdx.x) >> 5;
    int lane = threadIdx.x & 31;
    if (w >= n) return;
    int start = g_rowptr[w], end = g_rowptr[w + 1];

    float adl[H], m[H];
    #pragma unroll
    for (int h = 0; h < H; h++) { adl[h] = g_ad[w * H + h]; m[h] = -1e30f; }

    for (int j = start + lane; j < end; j += 32) {
        int s = g_col[j];
        #pragma unroll
        for (int h = 0; h < H; h++) {
            float e = g_as[s * H + h] + adl[h];
            e = (e > 0.f) ? e : 0.2f * e;
            m[h] = fmaxf(m[h], e);
        }
    }
    #pragma unroll
    for (int h = 0; h < H; h++)
        #pragma unroll
        for (int o = 16; o > 0; o >>= 1)
            m[h] = fmaxf(m[h], __shfl_xor_sync(0xffffffffu, m[h], o));

    float acc0[H], acc1[H], den[H];
    #pragma unroll
    for (int h = 0; h < H; h++) { acc0[h] = 0.f; acc1[h] = 0.f; den[h] = 0.f; }
    for (int j = start; j < end; j++) {
        int s = g_col[j];
        const float* hr = g_h + (size_t)s * (H * 64);
        #pragma unroll
        for (int h = 0; h < H; h++) {
            float e = g_as[s * H + h] + adl[h];
            e = (e > 0.f) ? e : 0.2f * e;
            float wgt = __expf(e - m[h]);
            den[h] += wgt;
            acc0[h] += wgt * hr[h * 64 + lane];
            acc1[h] += wgt * hr[h * 64 + 32 + lane];
        }
    }

    float y0 = 0.f, y1 = 0.f;
    #pragma unroll
    for (int h = 0; h < H; h++) {
        float inv = 1.f / (den[h] + 1e-16f);
        y0 += acc0[h] * inv;
        y1 += acc1[h] * inv;
    }
    const float invH = 1.f / (float)H;
    y0 *= invH; y1 *= invH;
    int c0 = lane, c1 = lane + 32;
    y0 += bias[c0]; y1 += bias[c1];
    if (BNRELU) {
        y0 = (y0 - bnm[c0]) * bng[c0] * rsqrtf(bnv[c0] + 1e-5f) + bnb[c0];
        y1 = (y1 - bnm[c1]) * bng[c1] * rsqrtf(bnv[c1] + 1e-5f) + bnb[c1];
        y0 = fmaxf(y0, 0.f);
        y1 = fmaxf(y1, 0.f);
    }
    out[(size_t)w * 64 + c0] = y0;
    out[(size_t)w * 64 + c1] = y1;
}

// ---------------- row softmax ----------------
__global__ void k_softmax(float* __restrict__ out, int n, int C) {
    const float* __restrict__ logits = g_h;
    int w = (blockIdx.x * blockDim.x + threadIdx.x) >> 5;
    int lane = threadIdx.x & 31;
    if (w >= n) return;
    float v0 = (lane < C) ? logits[(size_t)w * C + lane] : -1e30f;
    float v1 = (lane + 32 < C) ? logits[(size_t)w * C + lane + 32] : -1e30f;
    float mx = fmaxf(v0, v1);
    #pragma unroll
    for (int o = 16; o > 0; o >>= 1) mx = fmaxf(mx, __shfl_xor_sync(0xffffffffu, mx, o));
    float e0 = (lane < C) ? __expf(v0 - mx) : 0.f;
    float e1 = (lane + 32 < C) ? __expf(v1 - mx) : 0.f;
    float s = e0 + e1;
    #pragma unroll
    for (int o = 16; o > 0; o >>= 1) s += __shfl_xor_sync(0xffffffffu, s, o);
    float inv = 1.f / s;
    if (lane < C) out[(size_t)w * C + lane] = e0 * inv;
    if (lane + 32 < C) out[(size_t)w * C + lane + 32] = e1 * inv;
}

// ---------------- host orchestration ----------------
extern "C" void kernel_launch(void* const* d_in, const int* in_sizes, int n_in,
                              void* d_out, int out_size) {
    const float* x   = (const float*)d_in[0];
    const void*  ei  = d_in[1];
    const float* W1  = (const float*)d_in[2];
    const float* as1 = (const float*)d_in[3];
    const float* ad1 = (const float*)d_in[4];
    const float* b1  = (const float*)d_in[5];
    const float* W2  = (const float*)d_in[6];
    const float* as2 = (const float*)d_in[7];
    const float* ad2 = (const float*)d_in[8];
    const float* b2  = (const float*)d_in[9];
    const float* W3  = (const float*)d_in[10];
    const float* as3 = (const float*)d_in[11];
    const float* ad3 = (const float*)d_in[12];
    const float* b3  = (const float*)d_in[13];
    const float* bn1g = (const float*)d_in[14];
    const float* bn1b = (const float*)d_in[15];
    const float* bn1m = (const float*)d_in[16];
    const float* bn1v = (const float*)d_in[17];
    const float* bn2g = (const float*)d_in[18];
    const float* bn2b = (const float*)d_in[19];
    const float* bn2m = (const float*)d_in[20];
    const float* bn2v = (const float*)d_in[21];
    const float* cW1 = (const float*)d_in[22];
    const float* cb1 = (const float*)d_in[23];
    const float* cW2 = (const float*)d_in[24];
    const float* cb2 = (const float*)d_in[25];

    int n = in_sizes[0] / 256;   // 50000
    int E = in_sizes[1] / 2;     // 400000
    float* out = (float*)d_out;
    int nblk = (n + 1023) / 1024;

    // CSR build
    k_detect<<<1, 32>>>(ei, n);
    k_initdeg<<<(n + 255) / 256, 256>>>(n);
    k_hist<<<(E + 255) / 256, 256>>>(ei, E, n);
    k_scanA<<<nblk, 1024>>>(n);
    k_scanB<<<1, 32>>>(nblk, n);
    k_scanC<<<(n + 255) / 256, 256>>>(n);
    k_fill<<<(E + n + 255) / 256, 256>>>(ei, E, n);

    // layer 1: H=8  (h = x @ W1 -> g_h[n x 512], bf16-split tensor GEMM)
    k_cvtA<<<(n * 256 + 255) / 256, 256>>>(x, -1, n * 256);
    k_cvtB<<<(256 * 512 + 255) / 256, 256>>>(W1, 256 * 512);
    {
        dim3 grid(512 / 128, (n + 127) / 128);
        k_bmma<<<grid, 256>>>(0, n, 512, 256);
    }
    k_attn<<<(n * 8 * 32 + 255) / 256, 256>>>(as1, ad1, n, 8);
    k_gather<8, true><<<(n * 32 + 255) / 256, 256>>>(b1, bn1g, bn1b, bn1m, bn1v, 1, n);

    // layer 2: H=4  (h = f1 @ W2 -> g_h[n x 256], bf16-split tensor GEMM)
    k_cvtA<<<(n * 64 + 255) / 256, 256>>>(nullptr, 1, n * 64);
    k_cvtB<<<(64 * 256 + 255) / 256, 256>>>(W2, 64 * 256);
    {
        dim3 grid(256 / 128, (n + 127) / 128);
        k_bmma<<<grid, 256>>>(0, n, 256, 64);
    }
    k_attn<<<(n * 4 * 32 + 255) / 256, 256>>>(as2, ad2, n, 4);
    k_gather<4, true><<<(n * 32 + 255) / 256, 256>>>(b2, bn2g, bn2b, bn2m, bn2v, 2, n);

    // layer 3: H=1, concat  (h = f2 @ W3 -> g_h[n x 64])
    {
        dim3 grid(1, (n + 63) / 64);
        k_sgemm<false, false><<<grid, 256>>>(nullptr, W3, nullptr, 2, 0, n, 64, 64);
    }
    k_attn<<<(n * 1 * 32 + 255) / 256, 256>>>(as3, ad3, n, 1);
    k_gather<1, false><<<(n * 32 + 255) / 256, 256>>>(b3, nullptr, nullptr, nullptr, nullptr, 1, n);

    // classifier
    {
        dim3 grid(1, (n + 63) / 64);
        k_sgemm<true, true><<<grid, 256>>>(nullptr, cW1, cb1, 1, 2, n, 64, 64);
    }
    {
        dim3 grid(1, (n + 63) / 64);
        k_sgemm<true, false><<<grid, 256>>>(nullptr, cW2, cb2, 2, 0, n, 50, 64);
    }
    k_softmax<<<(n * 32 + 255) / 256, 256>>>(out, n, 50);
}